// round 8
// baseline (speedup 1.0000x reference)
#include <cuda_runtime.h>
#include <math.h>

#define D_MODEL 1024
#define NHEADS  16
#define DK      64
#define BATCH   2
#define SEQ     2048
#define HEAD_ELEMS (BATCH * NHEADS * SEQ * DK)   // 4,194,304 floats (16 MB)

// Scratch: __device__ globals (allocation guards forbid cudaMalloc)
__device__ float g_Qh[HEAD_ELEMS];
__device__ float g_Kh[HEAD_ELEMS];
__device__ float g_Vh[HEAD_ELEMS];
__device__ float g_ctx[HEAD_ELEMS];

// ---------------------------------------------------------------------------
// Kernel 1: fused QKV head projections.
//   Qh[b,h,t,k] = sum_d X[b,t,d] * W[h,d,k] + bias[h,k]
// Treated as GEMM M=B*T=4096, N=H*DK=1024, K=D_MODEL=1024.
// W is head-blocked: element (d, n) lives at W[(n>>6)*D_MODEL*DK + d*DK + (n&63)].
// blockIdx.z selects Q / K / V.
// Tile 128x128x8, 256 threads, 8x8 microtile, register prefetch of next k-slice.
// ---------------------------------------------------------------------------
__global__ __launch_bounds__(256)
void proj_kernel(const float* __restrict__ Qin, const float* __restrict__ Kin,
                 const float* __restrict__ Vin,
                 const float* __restrict__ Wq, const float* __restrict__ Wk,
                 const float* __restrict__ Wv,
                 const float* __restrict__ bq, const float* __restrict__ bk,
                 const float* __restrict__ bv)
{
    const float* A;
    const float* W;
    const float* bias;
    float* C;
    if (blockIdx.z == 0)      { A = Qin; W = Wq; bias = bq; C = g_Qh; }
    else if (blockIdx.z == 1) { A = Kin; W = Wk; bias = bk; C = g_Kh; }
    else                      { A = Vin; W = Wv; bias = bv; C = g_Vh; }

    __shared__ __align__(16) float As[8][128];
    __shared__ __align__(16) float Bs[8][128];

    const int tid  = threadIdx.x;
    const int m0   = blockIdx.y * 128;
    const int n0   = blockIdx.x * 128;
    const int arow = tid >> 1;            // 0..127
    const int acol = (tid & 1) * 4;       // 0 / 4
    const int brow = tid >> 5;            // 0..7
    const int bcol = (tid & 31) * 4;      // 0..124
    const int tx   = tid & 15;
    const int ty   = tid >> 4;

    float acc[8][8];
#pragma unroll
    for (int i = 0; i < 8; i++)
#pragma unroll
        for (int j = 0; j < 8; j++) acc[i][j] = 0.0f;

    const float* Aptr = A + (size_t)(m0 + arow) * D_MODEL + acol;
    const int    nB   = n0 + bcol;
    const float* Wptr = W + (size_t)(nB >> 6) * (D_MODEL * DK) + (nB & 63);

    float4 aReg = *(const float4*)(Aptr);
    float4 bReg = *(const float4*)(Wptr + brow * DK);

    for (int k0 = 0; k0 < D_MODEL; k0 += 8) {
        __syncthreads();
        As[acol + 0][arow] = aReg.x;
        As[acol + 1][arow] = aReg.y;
        As[acol + 2][arow] = aReg.z;
        As[acol + 3][arow] = aReg.w;
        *(float4*)&Bs[brow][bcol] = bReg;
        __syncthreads();

        if (k0 + 8 < D_MODEL) {  // prefetch next slice (overlaps with compute)
            aReg = *(const float4*)(Aptr + k0 + 8);
            bReg = *(const float4*)(Wptr + (size_t)(k0 + 8 + brow) * DK);
        }

#pragma unroll
        for (int kk = 0; kk < 8; kk++) {
            float af[8], bf[8];
#pragma unroll
            for (int i = 0; i < 8; i++) af[i] = As[kk][ty * 8 + i];
#pragma unroll
            for (int j = 0; j < 8; j++) bf[j] = Bs[kk][tx * 8 + j];
#pragma unroll
            for (int i = 0; i < 8; i++)
#pragma unroll
                for (int j = 0; j < 8; j++)
                    acc[i][j] = fmaf(af[i], bf[j], acc[i][j]);
        }
    }

    // Epilogue: scatter into [B,H,T,DK] layout, add bias (bias flat = [H*DK])
#pragma unroll
    for (int i = 0; i < 8; i++) {
        const int m = m0 + ty * 8 + i;
        const int b = m >> 11;
        const int t = m & (SEQ - 1);
#pragma unroll
        for (int j = 0; j < 8; j++) {
            const int n = n0 + tx * 8 + j;
            const int h = n >> 6;
            const int k = n & 63;
            C[(((size_t)(b * NHEADS + h)) * SEQ + t) * DK + k] = acc[i][j] + bias[n];
        }
    }
}

// ---------------------------------------------------------------------------
// Kernel 2: flash attention per (b,h).
// Block: 128 queries x full key loop (tiles of 64). 256 threads, microtile 8x4.
// Online softmax (exact), P staged through SMEM for the PV GEMM.
// ---------------------------------------------------------------------------
__global__ __launch_bounds__(256, 2)
void attn_kernel()
{
    extern __shared__ float sm[];
    float* Qs = sm;                       // [128][65]
    float* Ks = Qs + 128 * 65;            // [64][65]
    float* Vs = Ks + 64 * 65;             // [64][64]  (unpadded: float4-aligned rows)
    float* Ps = Vs + 64 * 64;             // [128][65]

    const int bh = blockIdx.y;            // 0..B*H-1
    const int q0 = blockIdx.x * 128;
    const float* Qbase = g_Qh + (size_t)bh * SEQ * DK;
    const float* Kbase = g_Kh + (size_t)bh * SEQ * DK;
    const float* Vbase = g_Vh + (size_t)bh * SEQ * DK;
    float*       Cbase = g_ctx + (size_t)bh * SEQ * DK;

    const int tid = threadIdx.x;
    const int tx  = tid & 15;             // key/dk column group (4 cols)
    const int ty  = tid >> 4;             // query row group (8 rows)
    const float scale = 0.125f;           // 1/sqrt(64)

    // Load Q tile (128x64) once
#pragma unroll
    for (int i = 0; i < 8; i++) {
        const int idx = tid + i * 256;
        const int r   = idx >> 4;
        const int c   = (idx & 15) * 4;
        float4 v = *(const float4*)(Qbase + (size_t)(q0 + r) * DK + c);
        Qs[r * 65 + c + 0] = v.x;
        Qs[r * 65 + c + 1] = v.y;
        Qs[r * 65 + c + 2] = v.z;
        Qs[r * 65 + c + 3] = v.w;
    }

    float m_i[8], l_i[8], O[8][4];
#pragma unroll
    for (int i = 0; i < 8; i++) {
        m_i[i] = -1e30f;
        l_i[i] = 0.0f;
#pragma unroll
        for (int j = 0; j < 4; j++) O[i][j] = 0.0f;
    }

    for (int s0 = 0; s0 < SEQ; s0 += 64) {
        __syncthreads();   // previous PV done before overwriting Ks/Vs
        // Load K,V tiles (64x64 each)
#pragma unroll
        for (int i = 0; i < 4; i++) {
            const int idx = tid + i * 256;
            const int r   = idx >> 4;
            const int c   = (idx & 15) * 4;
            float4 kv = *(const float4*)(Kbase + (size_t)(s0 + r) * DK + c);
            Ks[r * 65 + c + 0] = kv.x;
            Ks[r * 65 + c + 1] = kv.y;
            Ks[r * 65 + c + 2] = kv.z;
            Ks[r * 65 + c + 3] = kv.w;
            float4 vv = *(const float4*)(Vbase + (size_t)(s0 + r) * DK + c);
            *(float4*)(Vs + r * 64 + c) = vv;
        }
        __syncthreads();

        // S = Q @ K^T  (128x64 tile, inner dim 64)
        float s_acc[8][4];
#pragma unroll
        for (int i = 0; i < 8; i++)
#pragma unroll
            for (int j = 0; j < 4; j++) s_acc[i][j] = 0.0f;

#pragma unroll 4
        for (int kk = 0; kk < 64; kk++) {
            float a[8], bv[4];
#pragma unroll
            for (int i = 0; i < 8; i++) a[i] = Qs[(ty * 8 + i) * 65 + kk];
#pragma unroll
            for (int j = 0; j < 4; j++) bv[j] = Ks[(tx * 4 + j) * 65 + kk];
#pragma unroll
            for (int i = 0; i < 8; i++)
#pragma unroll
                for (int j = 0; j < 4; j++)
                    s_acc[i][j] = fmaf(a[i], bv[j], s_acc[i][j]);
        }

        // Online softmax per query row (row spread over 16 lanes, same-ty group)
#pragma unroll
        for (int i = 0; i < 8; i++) {
            float mt = -1e30f;
#pragma unroll
            for (int j = 0; j < 4; j++) {
                s_acc[i][j] *= scale;
                mt = fmaxf(mt, s_acc[i][j]);
            }
#pragma unroll
            for (int off = 8; off >= 1; off >>= 1)
                mt = fmaxf(mt, __shfl_xor_sync(0xffffffffu, mt, off));

            const float m_new = fmaxf(m_i[i], mt);
            const float alpha = __expf(m_i[i] - m_new);
            float rs = 0.0f;
#pragma unroll
            for (int j = 0; j < 4; j++) {
                const float p = __expf(s_acc[i][j] - m_new);
                s_acc[i][j] = p;
                rs += p;
            }
#pragma unroll
            for (int off = 8; off >= 1; off >>= 1)
                rs += __shfl_xor_sync(0xffffffffu, rs, off);

            l_i[i] = l_i[i] * alpha + rs;
            m_i[i] = m_new;
#pragma unroll
            for (int j = 0; j < 4; j++) O[i][j] *= alpha;
#pragma unroll
            for (int j = 0; j < 4; j++)
                Ps[(ty * 8 + i) * 65 + tx * 4 + j] = s_acc[i][j];
        }
        __syncthreads();

        // O += P @ V  (128x64 += 128x64 @ 64x64)
#pragma unroll 4
        for (int s = 0; s < 64; s++) {
            float a[8];
#pragma unroll
            for (int i = 0; i < 8; i++) a[i] = Ps[(ty * 8 + i) * 65 + s];
            const float4 vv = *(const float4*)(Vs + s * 64 + tx * 4);
#pragma unroll
            for (int i = 0; i < 8; i++) {
                O[i][0] = fmaf(a[i], vv.x, O[i][0]);
                O[i][1] = fmaf(a[i], vv.y, O[i][1]);
                O[i][2] = fmaf(a[i], vv.z, O[i][2]);
                O[i][3] = fmaf(a[i], vv.w, O[i][3]);
            }
        }
    }

    // Epilogue: normalize, write ctx[b,h,t,k]
#pragma unroll
    for (int i = 0; i < 8; i++) {
        const float inv = 1.0f / l_i[i];
        const int r = q0 + ty * 8 + i;
#pragma unroll
        for (int j = 0; j < 4; j++)
            Cbase[(size_t)r * DK + tx * 4 + j] = O[i][j] * inv;
    }
}

// ---------------------------------------------------------------------------
// Kernel 3: output projection.
//   x = ctx viewed flat [4096, 1024] (matches the reference's transpose-free
//   reshape exactly, since ctx is stored [B,H,T,dk] contiguous).
//   out[m, o] = sum_j x[m, j] * Wo[o, j] + bo[o]        (NT GEMM)
// ---------------------------------------------------------------------------
__global__ __launch_bounds__(256)
void out_kernel(float* __restrict__ Out, const float* __restrict__ Wo,
                const float* __restrict__ bo)
{
    __shared__ __align__(16) float As[8][128];
    __shared__ __align__(16) float Bs[8][128];

    const float* A = g_ctx;
    const int tid  = threadIdx.x;
    const int m0   = blockIdx.y * 128;
    const int n0   = blockIdx.x * 128;
    const int arow = tid >> 1;
    const int acol = (tid & 1) * 4;
    const int wrow = tid >> 1;            // local n index (0..127)
    const int wcol = (tid & 1) * 4;       // k offset (0 / 4)
    const int tx   = tid & 15;
    const int ty   = tid >> 4;

    float acc[8][8];
#pragma unroll
    for (int i = 0; i < 8; i++)
#pragma unroll
        for (int j = 0; j < 8; j++) acc[i][j] = 0.0f;

    const float* Aptr = A + (size_t)(m0 + arow) * D_MODEL + acol;
    const float* Wptr = Wo + (size_t)(n0 + wrow) * D_MODEL + wcol;

    float4 aReg = *(const float4*)(Aptr);
    float4 bReg = *(const float4*)(Wptr);

    for (int k0 = 0; k0 < D_MODEL; k0 += 8) {
        __syncthreads();
        As[acol + 0][arow] = aReg.x;
        As[acol + 1][arow] = aReg.y;
        As[acol + 2][arow] = aReg.z;
        As[acol + 3][arow] = aReg.w;
        Bs[wcol + 0][wrow] = bReg.x;      // transposed store: Bs[k][n_local]
        Bs[wcol + 1][wrow] = bReg.y;
        Bs[wcol + 2][wrow] = bReg.z;
        Bs[wcol + 3][wrow] = bReg.w;
        __syncthreads();

        if (k0 + 8 < D_MODEL) {
            aReg = *(const float4*)(Aptr + k0 + 8);
            bReg = *(const float4*)(Wptr + k0 + 8);
        }

#pragma unroll
        for (int kk = 0; kk < 8; kk++) {
            float af[8], bf[8];
#pragma unroll
            for (int i = 0; i < 8; i++) af[i] = As[kk][ty * 8 + i];
#pragma unroll
            for (int j = 0; j < 8; j++) bf[j] = Bs[kk][tx * 8 + j];
#pragma unroll
            for (int i = 0; i < 8; i++)
#pragma unroll
                for (int j = 0; j < 8; j++)
                    acc[i][j] = fmaf(af[i], bf[j], acc[i][j]);
        }
    }

#pragma unroll
    for (int i = 0; i < 8; i++) {
        const int m = m0 + ty * 8 + i;
#pragma unroll
        for (int j = 0; j < 8; j++) {
            const int n = n0 + tx * 8 + j;
            Out[(size_t)m * D_MODEL + n] = acc[i][j] + bo[n];
        }
    }
}

// ---------------------------------------------------------------------------
extern "C" void kernel_launch(void* const* d_in, const int* in_sizes, int n_in,
                              void* d_out, int out_size)
{
    (void)in_sizes; (void)n_in; (void)out_size;
    const float* Q  = (const float*)d_in[0];
    const float* K  = (const float*)d_in[1];
    const float* V  = (const float*)d_in[2];
    const float* Wq = (const float*)d_in[3];
    const float* bq = (const float*)d_in[4];
    const float* Wk = (const float*)d_in[5];
    const float* bk = (const float*)d_in[6];
    const float* Wv = (const float*)d_in[7];
    const float* bv = (const float*)d_in[8];
    const float* Wo = (const float*)d_in[9];
    const float* bo = (const float*)d_in[10];
    float* Out = (float*)d_out;

    // QKV projections: grid (N/128, M/128, 3)
    proj_kernel<<<dim3(D_MODEL / 128, (BATCH * SEQ) / 128, 3), 256>>>(
        Q, K, V, Wq, Wk, Wv, bq, bk, bv);

    // Flash attention: grid (T/128, B*H), ~99.6 KB dynamic smem
    const int ATTN_SMEM = (128 * 65 + 64 * 65 + 64 * 64 + 128 * 65) * (int)sizeof(float);
    cudaFuncSetAttribute((const void*)attn_kernel,
                         cudaFuncAttributeMaxDynamicSharedMemorySize, ATTN_SMEM);
    attn_kernel<<<dim3(SEQ / 128, BATCH * NHEADS), 256, ATTN_SMEM>>>();

    // Output projection
    out_kernel<<<dim3(D_MODEL / 128, (BATCH * SEQ) / 128), 256>>>(Out, Wo, bo);
}